// round 1
// baseline (speedup 1.0000x reference)
#include <cuda_runtime.h>
#include <cstdint>

// Problem dims
#define BV   64
#define TT   500
#define FIN  1250
#define HH   512
#define OO   2
#define MM   (BV * TT)   // 32000

// Neuron constants (fp32 nearest of exp(-1/10), exp(-1))
#define DSYN  0.9048374180359595f
#define DREF  0.36787944117144233f
#define THETA 10.0f

// Scratch (device globals: allocation-free rule)
__device__ float g_u1[(size_t)MM * HH];   // 64 MB
__device__ float g_s1[(size_t)MM * HH];   // 64 MB
__device__ float g_u2[(size_t)MM * OO];   // 256 KB

// ---------------------------------------------------------------------------
// K1: U1[m,h] = sum_f X[m,f] * W1[h,f]
// 128x128x8 block tile, 256 threads, 8x8 per thread.
// ---------------------------------------------------------------------------
#define BM 128
#define BN 128
#define BK 8
#define TM 8
#define TN 8

__global__ __launch_bounds__(256) void gemm1_kernel(
    const float* __restrict__ X, const float* __restrict__ W1,
    float* __restrict__ U)
{
    __shared__ float As[BK][BM];
    __shared__ float Bs[BK][BN];

    const int tid      = threadIdx.x;
    const int blockCol = blockIdx.x;   // over HH / BN = 4
    const int blockRow = blockIdx.y;   // over MM / BM = 250
    const int tx = tid & 15;           // 0..15
    const int ty = tid >> 4;           // 0..15

    float acc[TM][TN];
#pragma unroll
    for (int i = 0; i < TM; i++)
#pragma unroll
        for (int j = 0; j < TN; j++) acc[i][j] = 0.0f;

    // load mapping: each thread loads 4 scalars of A and 4 of B per k-tile
    const int lrow = tid >> 1;          // 0..127
    const int lcol = (tid & 1) * 4;     // 0 or 4

    const float* Xb = X  + (size_t)(blockRow * BM + lrow) * FIN;
    const float* Wb = W1 + (size_t)(blockCol * BN + lrow) * FIN;

    for (int kt = 0; kt < FIN; kt += BK) {
#pragma unroll
        for (int j = 0; j < 4; j++) {
            int k = kt + lcol + j;
            float av = 0.0f, bv = 0.0f;
            if (k < FIN) { av = Xb[k]; bv = Wb[k]; }
            As[lcol + j][lrow] = av;
            Bs[lcol + j][lrow] = bv;
        }
        __syncthreads();

#pragma unroll
        for (int kk = 0; kk < BK; kk++) {
            float a[TM], b[TN];
#pragma unroll
            for (int i = 0; i < TM; i++) a[i] = As[kk][ty * TM + i];
#pragma unroll
            for (int j = 0; j < TN; j++) b[j] = Bs[kk][tx * TN + j];
#pragma unroll
            for (int i = 0; i < TM; i++)
#pragma unroll
                for (int j = 0; j < TN; j++) acc[i][j] += a[i] * b[j];
        }
        __syncthreads();
    }

    float* Ub = U + (size_t)(blockRow * BM + ty * TM) * HH
                  + (size_t)(blockCol * BN + tx * TN);
#pragma unroll
    for (int i = 0; i < TM; i++)
#pragma unroll
        for (int j = 0; j < TN; j++) Ub[(size_t)i * HH + j] = acc[i][j];
}

// ---------------------------------------------------------------------------
// K2: fused PSP + spike scan, layer 1. One thread per (b, h) chain.
//   p[t] = d*p[t-1] + u[t];  v = p + r;  s = (v >= theta);
//   r = dref*(r - 2*theta*s)
// ---------------------------------------------------------------------------
__global__ __launch_bounds__(512) void scan1_kernel(
    const float* __restrict__ U1, float* __restrict__ S1)
{
    const int b = blockIdx.x;     // 64
    const int h = threadIdx.x;    // 512
    const float* up = U1 + (size_t)b * TT * HH + h;
    float*       sp = S1 + (size_t)b * TT * HH + h;

    float p = 0.0f, r = 0.0f;
#pragma unroll 4
    for (int t = 0; t < TT; t++) {
        float u = up[(size_t)t * HH];
        p = DSYN * p + u;
        float v = p + r;
        float s = (v >= THETA) ? 1.0f : 0.0f;
        r = DREF * (r - 2.0f * THETA * s);
        sp[(size_t)t * HH] = s;
    }
}

// ---------------------------------------------------------------------------
// K3: U2[m,o] = sum_h S1[m,h] * W2[o,h]. One warp per row m.
// ---------------------------------------------------------------------------
__global__ __launch_bounds__(256) void gemm2_kernel(
    const float* __restrict__ S1, const float* __restrict__ W2,
    float* __restrict__ U2)
{
    const int gwarp = (blockIdx.x * blockDim.x + threadIdx.x) >> 5;
    const int lane  = threadIdx.x & 31;
    if (gwarp >= MM) return;

    const float* s = S1 + (size_t)gwarp * HH;
    float a0 = 0.0f, a1 = 0.0f;
#pragma unroll
    for (int h = lane; h < HH; h += 32) {
        float sv = s[h];
        a0 += sv * W2[h];
        a1 += sv * W2[HH + h];
    }
#pragma unroll
    for (int off = 16; off > 0; off >>= 1) {
        a0 += __shfl_xor_sync(0xFFFFFFFFu, a0, off);
        a1 += __shfl_xor_sync(0xFFFFFFFFu, a1, off);
    }
    if (lane == 0) {
        U2[(size_t)gwarp * OO + 0] = a0;
        U2[(size_t)gwarp * OO + 1] = a1;
    }
}

// ---------------------------------------------------------------------------
// K4: fused PSP + spike scan, layer 2. 128 chains (64 b x 2 o), 1 block.
// ---------------------------------------------------------------------------
__global__ __launch_bounds__(128) void scan2_kernel(
    const float* __restrict__ U2, float* __restrict__ out)
{
    const int i = threadIdx.x;    // 128
    const int b = i >> 1;
    const int o = i & 1;
    const float* up = U2  + (size_t)b * TT * OO + o;
    float*       op = out + (size_t)b * TT * OO + o;

    float p = 0.0f, r = 0.0f;
#pragma unroll 4
    for (int t = 0; t < TT; t++) {
        float u = up[(size_t)t * OO];
        p = DSYN * p + u;
        float v = p + r;
        float s = (v >= THETA) ? 1.0f : 0.0f;
        r = DREF * (r - 2.0f * THETA * s);
        op[(size_t)t * OO] = s;
    }
}

// ---------------------------------------------------------------------------
extern "C" void kernel_launch(void* const* d_in, const int* in_sizes, int n_in,
                              void* d_out, int out_size)
{
    const float* x  = (const float*)d_in[0];   // (64, 500, 1250)
    const float* W1 = (const float*)d_in[1];   // (512, 1250)
    const float* W2 = (const float*)d_in[2];   // (2, 512)
    float* out = (float*)d_out;                // (64, 500, 2)

    float* u1; cudaGetSymbolAddress((void**)&u1, g_u1);
    float* s1; cudaGetSymbolAddress((void**)&s1, g_s1);
    float* u2; cudaGetSymbolAddress((void**)&u2, g_u2);

    dim3 g1(HH / BN, MM / BM);           // (4, 250)
    gemm1_kernel<<<g1, 256>>>(x, W1, u1);

    scan1_kernel<<<BV, HH>>>(u1, s1);    // 64 blocks x 512 threads

    // 32000 warps -> 4000 blocks of 256 threads
    gemm2_kernel<<<(MM * 32 + 255) / 256, 256>>>(s1, W2, u2);

    scan2_kernel<<<1, 128>>>(u2, out);
}

// round 2
// speedup vs baseline: 3.8020x; 3.8020x over previous
#include <cuda_runtime.h>
#include <cuda_bf16.h>
#include <cstdint>

// Problem dims
#define BV   64
#define TT   500
#define FIN  1250
#define KP   1280          // FIN padded to multiple of 32
#define HH   512
#define OO   2
#define MM   (BV * TT)     // 32000

// Neuron constants
#define DSYN  0.9048374180359595f
#define DREF  0.36787944117144233f
#define THETA 10.0f

// Scratch (device globals: allocation-free rule)
__device__ __align__(16) __nv_bfloat16 g_xb [(size_t)MM * KP];   // 82 MB
__device__ __align__(16) __nv_bfloat16 g_w1b[(size_t)HH * KP];   // 1.3 MB
__device__ __align__(16) float          g_u1 [(size_t)MM * HH];  // 64 MB
__device__ __align__(16) __nv_bfloat16 g_s1 [(size_t)MM * HH];   // 32 MB
__device__ __align__(16) float          g_u2 [(size_t)MM * OO];  // 256 KB

// ---------------------------------------------------------------------------
// PTX helpers
// ---------------------------------------------------------------------------
__device__ __forceinline__ void ldsm_x4(uint32_t &r0, uint32_t &r1,
                                        uint32_t &r2, uint32_t &r3,
                                        uint32_t addr)
{
    asm volatile("ldmatrix.sync.aligned.m8n8.x4.shared.b16 {%0,%1,%2,%3}, [%4];"
                 : "=r"(r0), "=r"(r1), "=r"(r2), "=r"(r3) : "r"(addr));
}

__device__ __forceinline__ void mma16816(float* c, const uint32_t* a,
                                         const uint32_t b0, const uint32_t b1)
{
    asm volatile(
        "mma.sync.aligned.m16n8k16.row.col.f32.bf16.bf16.f32 "
        "{%0,%1,%2,%3}, {%4,%5,%6,%7}, {%8,%9}, {%0,%1,%2,%3};"
        : "+f"(c[0]), "+f"(c[1]), "+f"(c[2]), "+f"(c[3])
        : "r"(a[0]), "r"(a[1]), "r"(a[2]), "r"(a[3]), "r"(b0), "r"(b1));
}

// ---------------------------------------------------------------------------
// K0a: convert x fp32 -> bf16, pad K 1250 -> 1280 with zeros
// ---------------------------------------------------------------------------
__global__ __launch_bounds__(256) void cvt_x_kernel(
    const float* __restrict__ X, __nv_bfloat16* __restrict__ Xb)
{
    long i = (long)blockIdx.x * blockDim.x + threadIdx.x;
    if (i >= (long)MM * KP) return;
    int  k = (int)(i % KP);
    long m = i / KP;
    float v = (k < FIN) ? X[m * FIN + k] : 0.0f;
    Xb[i] = __float2bfloat16(v);
}

__global__ __launch_bounds__(256) void cvt_w1_kernel(
    const float* __restrict__ W, __nv_bfloat16* __restrict__ Wb)
{
    long i = (long)blockIdx.x * blockDim.x + threadIdx.x;
    if (i >= (long)HH * KP) return;
    int  k = (int)(i % KP);
    long h = i / KP;
    float v = (k < FIN) ? W[h * FIN + k] : 0.0f;
    Wb[i] = __float2bfloat16(v);
}

// ---------------------------------------------------------------------------
// K1: U1[m,h] = sum_k Xb[m,k] * W1b[h,k]   (bf16 HMMA, fp32 accum)
// Block tile 128(M) x 64(N) x 32(K); 8 warps as 4(m) x 2(n); warp tile 32x32.
// smem rows padded to 40 bf16 (80B) -> conflict-free ldmatrix.
// ---------------------------------------------------------------------------
#define LDA 40   // padded row length (bf16 elems) for 32-wide k tile

__global__ __launch_bounds__(256) void gemm1_mma_kernel(
    const __nv_bfloat16* __restrict__ Xb,
    const __nv_bfloat16* __restrict__ Wb,
    float* __restrict__ U)
{
    __shared__ __align__(16) __nv_bfloat16 As[128 * LDA];
    __shared__ __align__(16) __nv_bfloat16 Bs[ 64 * LDA];

    const int tid  = threadIdx.x;
    const int warp = tid >> 5;
    const int lane = tid & 31;
    const int wm   = warp >> 1;          // 0..3
    const int wn   = warp & 1;           // 0..1
    const int bm   = blockIdx.y * 128;
    const int bn   = blockIdx.x * 64;

    float acc[2][4][4];
#pragma unroll
    for (int i = 0; i < 2; i++)
#pragma unroll
        for (int j = 0; j < 4; j++)
#pragma unroll
            for (int q = 0; q < 4; q++) acc[i][j][q] = 0.0f;

    const uint32_t asB = (uint32_t)__cvta_generic_to_shared(As);
    const uint32_t bsB = (uint32_t)__cvta_generic_to_shared(Bs);

    // ldmatrix lane addresses (byte offsets within tile, fixed per lane)
    // A (.x4): rows 0-15 at colB 0 (lanes 0-15), rows 0-15 at colB 16 (lanes 16-31)
    const uint32_t aRow = (uint32_t)(wm * 32 + (lane & 15));
    const uint32_t aCol = (uint32_t)((lane >> 4) * 16);
    // B (.x4): groups of 8 lanes -> (n0-7,k0-7),(n0-7,k8-15),(n8-15,k0-7),(n8-15,k8-15)
    const uint32_t bRow = (uint32_t)(wn * 32 + ((lane >> 4) & 1) * 8 + (lane & 7));
    const uint32_t bCol = (uint32_t)(((lane >> 3) & 1) * 16);

    for (int kt = 0; kt < KP; kt += 32) {
        // --- global -> shared: A 128 rows x 64B, B 64 rows x 64B
#pragma unroll
        for (int i = 0; i < 2; i++) {
            int c  = tid + i * 256;          // 0..511
            int r  = c >> 2;
            int cc = c & 3;
            uint4 v = *(const uint4*)(Xb + (size_t)(bm + r) * KP + kt + cc * 8);
            *(uint4*)(As + r * LDA + cc * 8) = v;
        }
        {
            int r  = tid >> 2;               // 0..63
            int cc = tid & 3;
            uint4 v = *(const uint4*)(Wb + (size_t)(bn + r) * KP + kt + cc * 8);
            *(uint4*)(Bs + r * LDA + cc * 8) = v;
        }
        __syncthreads();

#pragma unroll
        for (int ks = 0; ks < 2; ks++) {
            uint32_t a[2][4];
#pragma unroll
            for (int mt = 0; mt < 2; mt++) {
                uint32_t addr = asB + (aRow + mt * 16) * (LDA * 2)
                                    + ks * 32 + aCol;
                ldsm_x4(a[mt][0], a[mt][1], a[mt][2], a[mt][3], addr);
            }
            uint32_t b[2][4];   // pair p covers n-tiles 2p (regs 0,1) and 2p+1 (regs 2,3)
#pragma unroll
            for (int p = 0; p < 2; p++) {
                uint32_t addr = bsB + (bRow + p * 16) * (LDA * 2)
                                    + ks * 32 + bCol;
                ldsm_x4(b[p][0], b[p][1], b[p][2], b[p][3], addr);
            }
#pragma unroll
            for (int mt = 0; mt < 2; mt++)
#pragma unroll
                for (int nt = 0; nt < 4; nt++)
                    mma16816(acc[mt][nt], a[mt],
                             b[nt >> 1][(nt & 1) * 2],
                             b[nt >> 1][(nt & 1) * 2 + 1]);
        }
        __syncthreads();
    }

    // epilogue: fp32 stores
    const int cr = lane >> 2;        // 0..7
    const int cc = (lane & 3) * 2;   // 0,2,4,6
#pragma unroll
    for (int mt = 0; mt < 2; mt++) {
#pragma unroll
        for (int nt = 0; nt < 4; nt++) {
            int row0 = bm + wm * 32 + mt * 16 + cr;
            int col  = bn + wn * 32 + nt * 8 + cc;
            float2 v01 = make_float2(acc[mt][nt][0], acc[mt][nt][1]);
            float2 v23 = make_float2(acc[mt][nt][2], acc[mt][nt][3]);
            *(float2*)(U + (size_t)row0 * HH + col)       = v01;
            *(float2*)(U + (size_t)(row0 + 8) * HH + col) = v23;
        }
    }
}

// ---------------------------------------------------------------------------
// K2: fused PSP + spike scan, layer 1. Chunked register prefetch (MLP=10).
// grid (64, 4), 128 threads; writes bf16 spikes (exact: 0/1).
// ---------------------------------------------------------------------------
__global__ __launch_bounds__(128) void scan1_kernel(
    const float* __restrict__ U1, __nv_bfloat16* __restrict__ S1)
{
    const int b = blockIdx.x;
    const int h = blockIdx.y * 128 + threadIdx.x;
    const float*   up = U1 + (size_t)b * TT * HH + h;
    __nv_bfloat16* sp = S1 + (size_t)b * TT * HH + h;

    float p = 0.0f, r = 0.0f;
    for (int t0 = 0; t0 < TT; t0 += 10) {
        float buf[10];
#pragma unroll
        for (int j = 0; j < 10; j++) buf[j] = up[(size_t)(t0 + j) * HH];
#pragma unroll
        for (int j = 0; j < 10; j++) {
            p = DSYN * p + buf[j];
            float v = p + r;
            float s = (v >= THETA) ? 1.0f : 0.0f;
            r = DREF * (r - 2.0f * THETA * s);
            sp[(size_t)(t0 + j) * HH] = __float2bfloat16(s);
        }
    }
}

// ---------------------------------------------------------------------------
// K3: U2[m,o] = sum_h S1[m,h] * W2[o,h]. Warp per row; W2 staged in smem.
// ---------------------------------------------------------------------------
__global__ __launch_bounds__(256) void gemm2_kernel(
    const __nv_bfloat16* __restrict__ S1, const float* __restrict__ W2,
    float* __restrict__ U2)
{
    __shared__ float w2s[OO * HH];
    for (int i = threadIdx.x; i < OO * HH; i += blockDim.x) w2s[i] = W2[i];
    __syncthreads();

    const int gwarp = (blockIdx.x * blockDim.x + threadIdx.x) >> 5;
    const int lane  = threadIdx.x & 31;
    if (gwarp >= MM) return;

    const __nv_bfloat16* s = S1 + (size_t)gwarp * HH;
    float a0 = 0.0f, a1 = 0.0f;
#pragma unroll
    for (int h = lane; h < HH; h += 32) {
        float sv = __bfloat162float(s[h]);
        a0 += sv * w2s[h];
        a1 += sv * w2s[HH + h];
    }
#pragma unroll
    for (int off = 16; off > 0; off >>= 1) {
        a0 += __shfl_xor_sync(0xFFFFFFFFu, a0, off);
        a1 += __shfl_xor_sync(0xFFFFFFFFu, a1, off);
    }
    if (lane == 0) {
        U2[(size_t)gwarp * OO + 0] = a0;
        U2[(size_t)gwarp * OO + 1] = a1;
    }
}

// ---------------------------------------------------------------------------
// K4: scan layer 2. 128 chains, chunked prefetch (MLP=20).
// ---------------------------------------------------------------------------
__global__ __launch_bounds__(128) void scan2_kernel(
    const float* __restrict__ U2, float* __restrict__ out)
{
    const int i = threadIdx.x;
    const int b = i >> 1;
    const int o = i & 1;
    const float* up = U2  + (size_t)b * TT * OO + o;
    float*       op = out + (size_t)b * TT * OO + o;

    float p = 0.0f, r = 0.0f;
    for (int t0 = 0; t0 < TT; t0 += 20) {
        float buf[20];
#pragma unroll
        for (int j = 0; j < 20; j++) buf[j] = up[(size_t)(t0 + j) * OO];
#pragma unroll
        for (int j = 0; j < 20; j++) {
            p = DSYN * p + buf[j];
            float v = p + r;
            float s = (v >= THETA) ? 1.0f : 0.0f;
            r = DREF * (r - 2.0f * THETA * s);
            op[(size_t)(t0 + j) * OO] = s;
        }
    }
}

// ---------------------------------------------------------------------------
extern "C" void kernel_launch(void* const* d_in, const int* in_sizes, int n_in,
                              void* d_out, int out_size)
{
    const float* x  = (const float*)d_in[0];   // (64, 500, 1250)
    const float* W1 = (const float*)d_in[1];   // (512, 1250)
    const float* W2 = (const float*)d_in[2];   // (2, 512)
    float* out = (float*)d_out;                // (64, 500, 2)

    __nv_bfloat16* xb;  cudaGetSymbolAddress((void**)&xb,  g_xb);
    __nv_bfloat16* w1b; cudaGetSymbolAddress((void**)&w1b, g_w1b);
    float*         u1;  cudaGetSymbolAddress((void**)&u1,  g_u1);
    __nv_bfloat16* s1;  cudaGetSymbolAddress((void**)&s1,  g_s1);
    float*         u2;  cudaGetSymbolAddress((void**)&u2,  g_u2);

    {
        long n = (long)MM * KP;
        cvt_x_kernel<<<(unsigned)((n + 255) / 256), 256>>>(x, xb);
    }
    {
        long n = (long)HH * KP;
        cvt_w1_kernel<<<(unsigned)((n + 255) / 256), 256>>>(W1, w1b);
    }

    dim3 g1(HH / 64, MM / 128);               // (8, 250)
    gemm1_mma_kernel<<<g1, 256>>>(xb, w1b, u1);

    dim3 g2(BV, HH / 128);                    // (64, 4)
    scan1_kernel<<<g2, 128>>>(u1, s1);

    gemm2_kernel<<<(MM * 32 + 255) / 256, 256>>>(s1, W2, u2);

    scan2_kernel<<<1, 128>>>(u2, out);
}